// round 14
// baseline (speedup 1.0000x reference)
#include <cuda_runtime.h>
#include <cstdint>

// ContinousActionDecoder, filter-and-rescue, int8 IMMA screen:
//  Phase 1: u8(biased,row) x s8(query) mma.sync m16n8k32 on unit-normalized
//           vectors; 128-bias folded into integer thresholds. Barrier-free
//           hot loop, register A-frags straight from GMEM, 2 CTAs/SM.
//  Emission margin 0.02 >> int8 rounding error; phase 2 rescores exactly.

#define KD      64
#define QMAX    128
#define BM      128
#define TPB     256
#define GRIDX   296
#define MARGIN  0.02f
#define SCL     16129.0f          // 127*127
#define CAP     (1 << 21)
#define SROWS   32
#define PGRID   148

__device__ unsigned long long g_best[QMAX];       // static zero-init
__device__ unsigned int g_seedkey[QMAX];
__device__ int g_ccnt;
__device__ unsigned long long g_cand[CAP];

__device__ __forceinline__ unsigned int fkey(float f) {
    unsigned int u = __float_as_uint(f);
    return (u & 0x80000000u) ? ~u : (u | 0x80000000u);
}
__device__ __forceinline__ float unfkey(unsigned int k) {
    unsigned int u = (k & 0x80000000u) ? (k ^ 0x80000000u) : ~k;
    return __uint_as_float(u);
}
// pack 4 floats (each in [1,255] after bias) to u8x4 via 2^23 magic FMA
__device__ __forceinline__ uint32_t pack_u8(float4 v, float s) {
    uint32_t u0 = __float_as_uint(fmaf(v.x, s, 8388736.0f));  // 2^23 + 128
    uint32_t u1 = __float_as_uint(fmaf(v.y, s, 8388736.0f));
    uint32_t u2 = __float_as_uint(fmaf(v.z, s, 8388736.0f));
    uint32_t u3 = __float_as_uint(fmaf(v.w, s, 8388736.0f));
    return __byte_perm(__byte_perm(u0, u1, 0x0040),
                       __byte_perm(u2, u3, 0x0040), 0x5410);
}
#define MMA_U8S8(d, a0,a1,a2,a3, b0,b1) \
    asm volatile("mma.sync.aligned.m16n8k32.row.col.s32.u8.s8.s32 " \
        "{%0,%1,%2,%3}, {%4,%5,%6,%7}, {%8,%9}, {%0,%1,%2,%3};" \
        : "+r"((d)[0]), "+r"((d)[1]), "+r"((d)[2]), "+r"((d)[3]) \
        : "r"(a0), "r"(a1), "r"(a2), "r"(a3), "r"(b0), "r"(b1))

#define EMIT_IF(cond, q, row, s) do {                                   \
    if (cond) {                                                         \
        atomicMax(&g_seedkey[(q)], fkey(s));                            \
        int _idx = atomicAdd(&g_ccnt, 1);                               \
        if (_idx < CAP)                                                 \
            g_cand[_idx] = ((unsigned long long)(unsigned)(q) << 32) |  \
                           (unsigned long long)(unsigned)(row);         \
    }                                                                   \
} while (0)

// ---------------- prepass: exact sample scores -> per-query seed ----------
__global__ void __launch_bounds__(256)
prepass(const float* __restrict__ actions, const float* __restrict__ pred,
        int N, int Q)
{
    __shared__ float qn[QMAX * KD];
    __shared__ float rows[SROWS * KD];
    __shared__ float rinv[SROWS];
    __shared__ float qinv[QMAX];
    __shared__ unsigned int skey[QMAX];

    const int tid = threadIdx.x;
    if (tid < QMAX) {
        float iv = 0.f;
        if (tid < Q) {
            float ss = 0.f;
            for (int k = 0; k < KD; ++k) {
                float v = pred[tid * KD + k];
                ss = fmaf(v, v, ss);
            }
            iv = (ss > 1e-30f) ? rsqrtf(ss) : 0.f;
        }
        qinv[tid] = iv;
        skey[tid] = 0u;
    }
    __syncthreads();
    for (int i = tid; i < QMAX * KD; i += 256) {
        int q = i >> 6, k = i & 63;
        qn[i] = (q < Q) ? pred[q * KD + k] * qinv[q] : 0.f;
    }
    const long long total = (long long)PGRID * SROWS;
    for (int i = tid; i < SROWS * 16; i += 256) {
        int r = i >> 4, k4 = i & 15;
        long long si = (long long)blockIdx.x * SROWS + r;
        long long gr = si * N / total;
        if (gr >= N) gr = N - 1;
        *(float4*)&rows[r * KD + k4 * 4] =
            ((const float4*)actions)[gr * (KD / 4) + k4];
    }
    __syncthreads();
    if (tid < SROWS) {
        float ss = 0.f;
        for (int k = 0; k < KD; ++k) {
            float v = rows[tid * KD + k];
            ss = fmaf(v, v, ss);
        }
        rinv[tid] = (ss > 1e-30f) ? rsqrtf(ss) : 0.f;
    }
    __syncthreads();

    const int rl = tid >> 3;
    const int qg = tid & 7;
    float4 rv[16];
#pragma unroll
    for (int k = 0; k < 16; ++k) rv[k] = *(const float4*)&rows[rl * KD + k * 4];
    const float ri = rinv[rl];
#pragma unroll
    for (int j = 0; j < 16; ++j) {
        int q = qg + j * 8;
        const float4* qp = (const float4*)&qn[q * KD];
        float dot = 0.f;
#pragma unroll
        for (int k = 0; k < 16; ++k) {
            float4 b = qp[k];
            dot = fmaf(rv[k].x, b.x, dot);
            dot = fmaf(rv[k].y, b.y, dot);
            dot = fmaf(rv[k].z, b.z, dot);
            dot = fmaf(rv[k].w, b.w, dot);
        }
        if (q < Q) atomicMax(&skey[q], fkey(dot * ri));
    }
    __syncthreads();
    if (tid < QMAX && tid < Q) atomicMax(&g_seedkey[tid], skey[tid]);
}

// ---------------- phase 1: int8 IMMA screen, barrier-free ------------------
// thread (rw=lane>>2, c4=lane&3) loads rows {R,R+8} as float4 at float4-idx
// c4 + 4m (m=0..3) -> exactly its u8 A-fragment k-groups {4c4, +16, +32, +48}.
__device__ __forceinline__ void load_rows(float4* L0, float4* L1,
                                          const float* __restrict__ actions,
                                          long long tile, int Rb, int rw,
                                          int c4, int N)
{
    long long r0 = tile * BM + Rb + rw;
    long long r1 = r0 + 8;
    if (r0 >= N) r0 = N - 1;
    if (r1 >= N) r1 = N - 1;
    const float4* p0 = (const float4*)(actions + r0 * KD) + c4;
    const float4* p1 = (const float4*)(actions + r1 * KD) + c4;
#pragma unroll
    for (int m = 0; m < 4; ++m) {
        L0[m] = p0[4 * m];
        L1[m] = p1[4 * m];
    }
}

extern "C" __global__ void __launch_bounds__(TPB, 2)
sim_argmax(const float* __restrict__ actions, const float* __restrict__ pred,
           int N, int Q)
{
    __shared__ float invb[QMAX];
    __shared__ int   ti_s[QMAX];     // integer thresholds (bias folded in)
    __shared__ int   sumb_s[QMAX];   // per-query sum of s8 query ints
    __shared__ uint2 Bf[1024];       // 8 KB s8 query frags

    const int tid  = threadIdx.x;
    const int lane = tid & 31;
    const int w    = tid >> 5;
    const int rw   = lane >> 2;
    const int c4   = lane & 3;
    const int Rb   = w * 16;

    if (tid < QMAX) {
        float iv = 0.f;
        if (tid < Q) {
            float ss = 0.f;
            for (int k = 0; k < KD; ++k) {
                float v = pred[tid * KD + k];
                ss = fmaf(v, v, ss);
            }
            iv = (ss > 1e-30f) ? rsqrtf(ss) : 0.f;
        }
        invb[tid] = iv;
        sumb_s[tid] = 0;
    }
    __syncthreads();

    // B fragments once: slot=(ks*16+nt)*32+lane -> uint2 {s8x4(k0..k0+3),
    // s8x4(k0+16..k0+19)}, k0 = ks*32 + 4*c4, q = nt*8 + rw. Accumulate sumb.
#pragma unroll
    for (int i = 0; i < 4; ++i) {
        int slot = tid + i * TPB;              // 0..1023
        int ks = slot >> 9;
        int nt = (slot >> 5) & 15;
        int l  = slot & 31;
        int q  = nt * 8 + (l >> 2);
        int k0 = ks * 32 + (l & 3) * 4;
        int bi[8];
        float iv = invb[q];
#pragma unroll
        for (int j = 0; j < 4; ++j) {
            bi[j]     = (q < Q) ? __float2int_rn(pred[q * KD + k0 + j] * iv * 127.f) : 0;
            bi[4 + j] = (q < Q) ? __float2int_rn(pred[q * KD + k0 + 16 + j] * iv * 127.f) : 0;
        }
        uint2 v;
        v.x = (bi[0] & 0xFF) | ((bi[1] & 0xFF) << 8) |
              ((bi[2] & 0xFF) << 16) | (bi[3] << 24);
        v.y = (bi[4] & 0xFF) | ((bi[5] & 0xFF) << 8) |
              ((bi[6] & 0xFF) << 16) | (bi[7] << 24);
        Bf[slot] = v;
        int s8sum = bi[0]+bi[1]+bi[2]+bi[3]+bi[4]+bi[5]+bi[6]+bi[7];
        if (q < Q && s8sum != 0) atomicAdd(&sumb_s[q], s8sum);
    }
    __syncthreads();

    // integer thresholds from global seeds (bias-correction folded in)
    if (tid < QMAX) {
        if (tid < Q) {
            float thr = unfkey(g_seedkey[tid]) - MARGIN;
            ti_s[tid] = (int)ceilf(thr * SCL) + 128 * sumb_s[tid];
        } else {
            ti_s[tid] = 0x7FFFFFFF;
        }
    }
    __syncthreads();                            // last barrier before loop

    const long long ntiles = ((long long)N + BM - 1) / BM;
    long long tile = blockIdx.x;

    float4 L0[4], L1[4];
    if (tile < ntiles) load_rows(L0, L1, actions, tile, Rb, rw, c4, N);

    int it = 0;
    for (; tile < ntiles; tile += GRIDX, ++it) {
        // ---- row norms (exact fp32) via 4-lane shuffle reduce
        float ss0 = 0.f, ss1 = 0.f;
#pragma unroll
        for (int m = 0; m < 4; ++m) {
            ss0 = fmaf(L0[m].x, L0[m].x, ss0);
            ss0 = fmaf(L0[m].y, L0[m].y, ss0);
            ss0 = fmaf(L0[m].z, L0[m].z, ss0);
            ss0 = fmaf(L0[m].w, L0[m].w, ss0);
            ss1 = fmaf(L1[m].x, L1[m].x, ss1);
            ss1 = fmaf(L1[m].y, L1[m].y, ss1);
            ss1 = fmaf(L1[m].z, L1[m].z, ss1);
            ss1 = fmaf(L1[m].w, L1[m].w, ss1);
        }
        ss0 += __shfl_xor_sync(0xffffffffu, ss0, 1);
        ss0 += __shfl_xor_sync(0xffffffffu, ss0, 2);
        ss1 += __shfl_xor_sync(0xffffffffu, ss1, 1);
        ss1 += __shfl_xor_sync(0xffffffffu, ss1, 2);
        float s0 = (ss0 > 1e-30f) ? rsqrtf(ss0) * 127.f : 0.f;
        float s1 = (ss1 > 1e-30f) ? rsqrtf(ss1) * 127.f : 0.f;

        // ---- pack biased-u8 A-frags in registers (magic FMA + prmt)
        uint32_t A0[4], A1[4];
#pragma unroll
        for (int m = 0; m < 4; ++m) {
            A0[m] = pack_u8(L0[m], s0);
            A1[m] = pack_u8(L1[m], s1);
        }

        // ---- prefetch next tile's rows
        long long tn = tile + GRIDX;
        load_rows(L0, L1, actions, (tn < ntiles) ? tn : tile, Rb, rw, c4, N);

        // ---- periodic threshold refresh (racing, monotone-safe)
        if ((it & 7) == 7) {
            for (int j = lane; j < QMAX; j += 32) {
                if (j < Q) {
                    float thr = unfkey(g_seedkey[j]) - MARGIN;
                    int v = (int)ceilf(thr * SCL) + 128 * sumb_s[j];
                    if (v > ti_s[j]) ti_s[j] = v;
                }
            }
        }

        const long long r0g = tile * BM + Rb + rw;
        const bool ok0 = (r0g < N), ok1 = (r0g + 8 < N);

#pragma unroll
        for (int hf = 0; hf < 2; ++hf) {
            int d[8][4];
#pragma unroll
            for (int n = 0; n < 8; ++n)
#pragma unroll
                for (int c = 0; c < 4; ++c) d[n][c] = 0;

#pragma unroll
            for (int ks = 0; ks < 2; ++ks) {
                uint32_t a0 = A0[2 * ks],     a1 = A1[2 * ks];
                uint32_t a2 = A0[2 * ks + 1], a3 = A1[2 * ks + 1];
#pragma unroll
                for (int n = 0; n < 8; ++n) {
                    uint2 b = Bf[(ks * 16 + hf * 8 + n) * 32 + lane];
                    MMA_U8S8(d[n], a0, a1, a2, a3, b.x, b.y);
                }
            }

            // branch-free integer screening over this hf's 32 values
            int mx = (int)0x80000000;
#pragma unroll
            for (int n = 0; n < 8; ++n) {
                int j = hf * 8 + n;
                int t0i = ti_s[j * 8 + 2 * c4];
                int t1i = ti_s[j * 8 + 2 * c4 + 1];
                int m01 = max(d[n][0] - t0i, d[n][1] - t1i);
                int m23 = max(d[n][2] - t0i, d[n][3] - t1i);
                mx = max(mx, max(m01, m23));
            }
            if (__any_sync(0xffffffffu, mx >= 0)) {
#pragma unroll
                for (int n = 0; n < 8; ++n) {
                    int j = hf * 8 + n;
                    int q0 = j * 8 + 2 * c4;
                    int t0i = ti_s[q0], t1i = ti_s[q0 + 1];
                    int sb0 = 128 * sumb_s[q0], sb1 = 128 * sumb_s[q0 + 1];
                    float s00 = (float)(d[n][0] - sb0) * (1.f / SCL);
                    float s01 = (float)(d[n][1] - sb1) * (1.f / SCL);
                    float s02 = (float)(d[n][2] - sb0) * (1.f / SCL);
                    float s03 = (float)(d[n][3] - sb1) * (1.f / SCL);
                    EMIT_IF(ok0 && d[n][0] >= t0i, q0,     r0g,     s00);
                    EMIT_IF(ok0 && d[n][1] >= t1i, q0 + 1, r0g,     s01);
                    EMIT_IF(ok1 && d[n][2] >= t0i, q0,     r0g + 8, s02);
                    EMIT_IF(ok1 && d[n][3] >= t1i, q0 + 1, r0g + 8, s03);
                }
            }
        }
    }
}

// ---------------- phase 2: exact rescore ----------------------------------
extern "C" __global__ void rescore(const float* __restrict__ actions,
                                   const float* __restrict__ pred, int N)
{
    int total = g_ccnt;
    if (total > CAP) total = CAP;
    const int stride = gridDim.x * blockDim.x;
    for (int i = blockIdx.x * blockDim.x + threadIdx.x; i < total; i += stride) {
        unsigned long long c = g_cand[i];
        int q = (int)(c >> 32);
        unsigned row = (unsigned)c;
        const float4* a = (const float4*)(actions + (size_t)row * KD);
        const float4* b = (const float4*)(pred + (size_t)q * KD);
        float dot = 0.f, na = 0.f;
#pragma unroll
        for (int j = 0; j < 16; ++j) {
            float4 av = a[j], bv = b[j];
            dot = fmaf(av.x, bv.x, dot);
            dot = fmaf(av.y, bv.y, dot);
            dot = fmaf(av.z, bv.z, dot);
            dot = fmaf(av.w, bv.w, dot);
            na = fmaf(av.x, av.x, na);
            na = fmaf(av.y, av.y, na);
            na = fmaf(av.z, av.z, na);
            na = fmaf(av.w, av.w, na);
        }
        float s = dot / sqrtf(fmaxf(na, 1e-30f));
        unsigned long long pk = ((unsigned long long)fkey(s) << 32) |
                                (unsigned long long)(~row);
        atomicMax(&g_best[q], pk);
    }
}

__global__ void gather(const float* __restrict__ actions,
                       float* __restrict__ out, int Q) {
    int q = blockIdx.x;
    int t = threadIdx.x;
    unsigned int idx = ~(unsigned int)(g_best[q] & 0xFFFFFFFFull);
    out[(size_t)q * KD + t] = actions[(size_t)idx * KD + t];
    __syncthreads();
    if (t == 0) {
        g_best[q] = 0ull;
        g_seedkey[q] = 0u;
        if (q == 0) g_ccnt = 0;
    }
}

extern "C" void kernel_launch(void* const* d_in, const int* in_sizes, int n_in,
                              void* d_out, int out_size) {
    int ip = 0, ia = 1;
    if (n_in >= 2 && in_sizes[0] > in_sizes[1]) { ip = 1; ia = 0; }
    const float* pred    = (const float*)d_in[ip];
    const float* actions = (const float*)d_in[ia];
    int Q = in_sizes[ip] / KD;
    if (Q > QMAX) Q = QMAX;
    int N = in_sizes[ia] / KD;

    prepass<<<PGRID, 256>>>(actions, pred, N, Q);
    sim_argmax<<<GRIDX, TPB>>>(actions, pred, N, Q);
    rescore<<<148, 256>>>(actions, pred, N);
    gather<<<Q, KD>>>(actions, (float*)d_out, Q);
}

// round 15
// speedup vs baseline: 1.1823x; 1.1823x over previous
#include <cuda_runtime.h>
#include <cuda_fp16.h>
#include <cstdint>

// ContinousActionDecoder, filter-and-rescue, software-pipelined fp16 screen:
//  Barrier-free hot loop, 2 CTAs/SM. A-fragments double-buffered in regs:
//  pack(t+1) and prefetch(t+2) issue BEFORE MMA+screen(t), so the norm/pack
//  dependency chain hides under the HMMA stream (no MMA-free phases).
//  Dynamic per-query thresholds seeded by exact prepass; exact fp32 rescore.

#define KD      64
#define QMAX    128
#define BM      128
#define TPB     256
#define GRIDX   296
#define MARGIN  1.5e-3f
#define CAP     (1 << 21)
#define SROWS   32
#define PGRID   148

__device__ unsigned long long g_best[QMAX];       // static zero-init
__device__ unsigned int g_seedkey[QMAX];
__device__ int g_ccnt;
__device__ unsigned long long g_cand[CAP];

__device__ __forceinline__ unsigned int fkey(float f) {
    unsigned int u = __float_as_uint(f);
    return (u & 0x80000000u) ? ~u : (u | 0x80000000u);
}
__device__ __forceinline__ float unfkey(unsigned int k) {
    unsigned int u = (k & 0x80000000u) ? (k ^ 0x80000000u) : ~k;
    return __uint_as_float(u);
}
__device__ __forceinline__ uint32_t h2pack(float lo, float hi) {
    uint32_t r;
    asm("cvt.rn.f16x2.f32 %0, %1, %2;" : "=r"(r) : "f"(hi), "f"(lo));
    return r;
}
#define MMA_F16(d, a0,a1,a2,a3, b0,b1) \
    asm volatile("mma.sync.aligned.m16n8k16.row.col.f32.f16.f16.f32 " \
        "{%0,%1,%2,%3}, {%4,%5,%6,%7}, {%8,%9}, {%0,%1,%2,%3};" \
        : "+f"((d)[0]), "+f"((d)[1]), "+f"((d)[2]), "+f"((d)[3]) \
        : "r"(a0), "r"(a1), "r"(a2), "r"(a3), "r"(b0), "r"(b1))

#define EMIT_IF(cond, q, row, s) do {                                   \
    if (cond) {                                                         \
        atomicMax(&g_seedkey[(q)], fkey(s));                            \
        int _idx = atomicAdd(&g_ccnt, 1);                               \
        if (_idx < CAP)                                                 \
            g_cand[_idx] = ((unsigned long long)(unsigned)(q) << 32) |  \
                           (unsigned long long)(unsigned)(row);         \
    }                                                                   \
} while (0)

// ---------------- prepass: exact sample scores -> per-query seed ----------
__global__ void __launch_bounds__(256)
prepass(const float* __restrict__ actions, const float* __restrict__ pred,
        int N, int Q)
{
    __shared__ float qn[QMAX * KD];
    __shared__ float rows[SROWS * KD];
    __shared__ float rinv[SROWS];
    __shared__ float qinv[QMAX];
    __shared__ unsigned int skey[QMAX];

    const int tid = threadIdx.x;
    if (tid < QMAX) {
        float iv = 0.f;
        if (tid < Q) {
            float ss = 0.f;
            for (int k = 0; k < KD; ++k) {
                float v = pred[tid * KD + k];
                ss = fmaf(v, v, ss);
            }
            iv = (ss > 1e-30f) ? rsqrtf(ss) : 0.f;
        }
        qinv[tid] = iv;
        skey[tid] = 0u;
    }
    __syncthreads();
    for (int i = tid; i < QMAX * KD; i += 256) {
        int q = i >> 6, k = i & 63;
        qn[i] = (q < Q) ? pred[q * KD + k] * qinv[q] : 0.f;
    }
    const long long total = (long long)PGRID * SROWS;
    for (int i = tid; i < SROWS * 16; i += 256) {
        int r = i >> 4, k4 = i & 15;
        long long si = (long long)blockIdx.x * SROWS + r;
        long long gr = si * N / total;
        if (gr >= N) gr = N - 1;
        *(float4*)&rows[r * KD + k4 * 4] =
            ((const float4*)actions)[gr * (KD / 4) + k4];
    }
    __syncthreads();
    if (tid < SROWS) {
        float ss = 0.f;
        for (int k = 0; k < KD; ++k) {
            float v = rows[tid * KD + k];
            ss = fmaf(v, v, ss);
        }
        rinv[tid] = (ss > 1e-30f) ? rsqrtf(ss) : 0.f;
    }
    __syncthreads();

    const int rl = tid >> 3;
    const int qg = tid & 7;
    float4 rv[16];
#pragma unroll
    for (int k = 0; k < 16; ++k) rv[k] = *(const float4*)&rows[rl * KD + k * 4];
    const float ri = rinv[rl];
#pragma unroll
    for (int j = 0; j < 16; ++j) {
        int q = qg + j * 8;
        const float4* qp = (const float4*)&qn[q * KD];
        float dot = 0.f;
#pragma unroll
        for (int k = 0; k < 16; ++k) {
            float4 b = qp[k];
            dot = fmaf(rv[k].x, b.x, dot);
            dot = fmaf(rv[k].y, b.y, dot);
            dot = fmaf(rv[k].z, b.z, dot);
            dot = fmaf(rv[k].w, b.w, dot);
        }
        if (q < Q) atomicMax(&skey[q], fkey(dot * ri));
    }
    __syncthreads();
    if (tid < QMAX && tid < Q) atomicMax(&g_seedkey[tid], skey[tid]);
}

// ---------------- phase 1: software-pipelined screened MMA -----------------
__device__ __forceinline__ void load_rows(float2* L0, float2* L1,
                                          const float* __restrict__ actions,
                                          long long tile, int Rb, int rw,
                                          int c4, int N)
{
    long long r0 = tile * BM + Rb + rw;
    long long r1 = r0 + 8;
    if (r0 >= N) r0 = N - 1;
    if (r1 >= N) r1 = N - 1;
    const float2* p0 = (const float2*)(actions + r0 * KD) + c4;
    const float2* p1 = (const float2*)(actions + r1 * KD) + c4;
#pragma unroll
    for (int m = 0; m < 8; ++m) {
        L0[m] = p0[4 * m];
        L1[m] = p1[4 * m];
    }
}

// norms (exact fp32) + unit-norm fp16 pack: L -> A[16] (A[ks*4+j])
__device__ __forceinline__ void pack16(const float2* L0, const float2* L1,
                                       uint32_t* A)
{
    float ss0 = 0.f, ss1 = 0.f;
#pragma unroll
    for (int m = 0; m < 8; ++m) {
        ss0 = fmaf(L0[m].x, L0[m].x, ss0);
        ss0 = fmaf(L0[m].y, L0[m].y, ss0);
        ss1 = fmaf(L1[m].x, L1[m].x, ss1);
        ss1 = fmaf(L1[m].y, L1[m].y, ss1);
    }
    ss0 += __shfl_xor_sync(0xffffffffu, ss0, 1);
    ss0 += __shfl_xor_sync(0xffffffffu, ss0, 2);
    ss1 += __shfl_xor_sync(0xffffffffu, ss1, 1);
    ss1 += __shfl_xor_sync(0xffffffffu, ss1, 2);
    float inv0 = (ss0 > 1e-30f) ? rsqrtf(ss0) : 0.f;
    float inv1 = (ss1 > 1e-30f) ? rsqrtf(ss1) : 0.f;
#pragma unroll
    for (int ks = 0; ks < 4; ++ks) {
        A[4 * ks + 0] = h2pack(L0[2 * ks].x * inv0,     L0[2 * ks].y * inv0);
        A[4 * ks + 1] = h2pack(L1[2 * ks].x * inv1,     L1[2 * ks].y * inv1);
        A[4 * ks + 2] = h2pack(L0[2 * ks + 1].x * inv0, L0[2 * ks + 1].y * inv0);
        A[4 * ks + 3] = h2pack(L1[2 * ks + 1].x * inv1, L1[2 * ks + 1].y * inv1);
    }
}

extern "C" __global__ void __launch_bounds__(TPB, 2)
sim_argmax(const float* __restrict__ actions, const float* __restrict__ pred,
           int N, int Q)
{
    __shared__ float invb[QMAX];
    __shared__ float tf_s[QMAX];
    __shared__ uint2 Bf[2048];                 // 16 KB query frags

    const int tid  = threadIdx.x;
    const int lane = tid & 31;
    const int w    = tid >> 5;
    const int rw   = lane >> 2;
    const int c4   = lane & 3;
    const int Rb   = w * 16;

    if (tid < QMAX) {
        float iv = 0.f;
        if (tid < Q) {
            float ss = 0.f;
            for (int k = 0; k < KD; ++k) {
                float v = pred[tid * KD + k];
                ss = fmaf(v, v, ss);
            }
            iv = (ss > 1e-30f) ? rsqrtf(ss) : 0.f;
        }
        invb[tid] = iv;
        tf_s[tid] = (tid < Q) ? (unfkey(g_seedkey[tid]) - MARGIN) : 3.4e38f;
    }
    __syncthreads();

    // B fragments once: [ks][nt][lane] -> uint2 {bh(k0,k1), bh(k+8)}
#pragma unroll
    for (int i = 0; i < 8; ++i) {
        int slot = tid + i * TPB;              // 0..2047
        int ks = slot >> 9;
        int nt = (slot >> 5) & 15;
        int l  = slot & 31;
        int q  = nt * 8 + (l >> 2);
        int k0 = ks * 16 + (l & 3) * 2;
        float iv = invb[q];
        float x0 = 0.f, x1 = 0.f, x2 = 0.f, x3 = 0.f;
        if (q < Q) {
            x0 = pred[q * KD + k0]     * iv;
            x1 = pred[q * KD + k0 + 1] * iv;
            x2 = pred[q * KD + k0 + 8] * iv;
            x3 = pred[q * KD + k0 + 9] * iv;
        }
        uint2 v;
        v.x = h2pack(x0, x1);
        v.y = h2pack(x2, x3);
        Bf[slot] = v;
    }
    __syncthreads();                            // last barrier before loop

    const long long ntiles = ((long long)N + BM - 1) / BM;
    long long tile = blockIdx.x;
    int it = 0;

    float2 L0[8], L1[8];
    uint32_t Aa[16], Ab[16];

    if (tile < ntiles) {
        load_rows(L0, L1, actions, tile, Rb, rw, c4, N);
        pack16(L0, L1, Aa);
        long long t1 = tile + GRIDX;
        load_rows(L0, L1, actions, (t1 < ntiles) ? t1 : tile, Rb, rw, c4, N);
    }

// body: pack A_NXT from L (tile+G), prefetch L(tile+2G), MMA+screen with A_CUR
#define BODY(A_CUR, A_NXT) do {                                              \
    if (tile + GRIDX < ntiles) pack16(L0, L1, A_NXT);                        \
    {                                                                        \
        long long t2 = tile + 2 * GRIDX;                                     \
        load_rows(L0, L1, actions, (t2 < ntiles) ? t2 : tile,                \
                  Rb, rw, c4, N);                                            \
    }                                                                        \
    if ((it & 7) == 7) {                                                     \
        for (int j = lane; j < QMAX; j += 32)                                \
            tf_s[j] = fmaxf(tf_s[j], unfkey(g_seedkey[j]) - MARGIN);         \
    }                                                                        \
    const long long r0g = tile * BM + Rb + rw;                               \
    const bool ok0 = (r0g < N), ok1 = (r0g + 8 < N);                         \
    _Pragma("unroll")                                                        \
    for (int hf = 0; hf < 2; ++hf) {                                         \
        float d[8][4];                                                       \
        _Pragma("unroll")                                                    \
        for (int n = 0; n < 8; ++n) {                                        \
            d[n][0] = 0.f; d[n][1] = 0.f; d[n][2] = 0.f; d[n][3] = 0.f;      \
        }                                                                    \
        _Pragma("unroll")                                                    \
        for (int ks = 0; ks < 4; ++ks) {                                     \
            _Pragma("unroll")                                                \
            for (int n = 0; n < 8; ++n) {                                    \
                uint2 b = Bf[(ks * 16 + hf * 8 + n) * 32 + lane];            \
                MMA_F16(d[n], (A_CUR)[4*ks], (A_CUR)[4*ks+1],                \
                        (A_CUR)[4*ks+2], (A_CUR)[4*ks+3], b.x, b.y);         \
            }                                                                \
        }                                                                    \
        float mx = -3.4e38f;                                                 \
        _Pragma("unroll")                                                    \
        for (int n = 0; n < 8; ++n) {                                        \
            int j = hf * 8 + n;                                              \
            float t0f = tf_s[j * 8 + 2 * c4];                                \
            float t1f = tf_s[j * 8 + 2 * c4 + 1];                            \
            float m01 = fmaxf(d[n][0] - t0f, d[n][1] - t1f);                 \
            float m23 = fmaxf(d[n][2] - t0f, d[n][3] - t1f);                 \
            mx = fmaxf(mx, fmaxf(m01, m23));                                 \
        }                                                                    \
        if (__any_sync(0xffffffffu, mx >= 0.f)) {                            \
            _Pragma("unroll")                                                \
            for (int n = 0; n < 8; ++n) {                                    \
                int j = hf * 8 + n;                                          \
                int q0 = j * 8 + 2 * c4;                                     \
                float t0f = tf_s[q0], t1f = tf_s[q0 + 1];                    \
                EMIT_IF(ok0 && d[n][0] >= t0f, q0,     r0g,     d[n][0]);    \
                EMIT_IF(ok0 && d[n][1] >= t1f, q0 + 1, r0g,     d[n][1]);    \
                EMIT_IF(ok1 && d[n][2] >= t0f, q0,     r0g + 8, d[n][2]);    \
                EMIT_IF(ok1 && d[n][3] >= t1f, q0 + 1, r0g + 8, d[n][3]);    \
            }                                                                \
        }                                                                    \
    }                                                                        \
    tile += GRIDX; ++it;                                                     \
} while (0)

    while (tile < ntiles) {
        BODY(Aa, Ab);
        if (tile >= ntiles) break;
        BODY(Ab, Aa);
    }
#undef BODY
}

// ---------------- phase 2: exact rescore ----------------------------------
extern "C" __global__ void rescore(const float* __restrict__ actions,
                                   const float* __restrict__ pred, int N)
{
    int total = g_ccnt;
    if (total > CAP) total = CAP;
    const int stride = gridDim.x * blockDim.x;
    for (int i = blockIdx.x * blockDim.x + threadIdx.x; i < total; i += stride) {
        unsigned long long c = g_cand[i];
        int q = (int)(c >> 32);
        unsigned row = (unsigned)c;
        const float4* a = (const float4*)(actions + (size_t)row * KD);
        const float4* b = (const float4*)(pred + (size_t)q * KD);
        float dot = 0.f, na = 0.f;
#pragma unroll
        for (int j = 0; j < 16; ++j) {
            float4 av = a[j], bv = b[j];
            dot = fmaf(av.x, bv.x, dot);
            dot = fmaf(av.y, bv.y, dot);
            dot = fmaf(av.z, bv.z, dot);
            dot = fmaf(av.w, bv.w, dot);
            na = fmaf(av.x, av.x, na);
            na = fmaf(av.y, av.y, na);
            na = fmaf(av.z, av.z, na);
            na = fmaf(av.w, av.w, na);
        }
        float s = dot / sqrtf(fmaxf(na, 1e-30f));
        unsigned long long pk = ((unsigned long long)fkey(s) << 32) |
                                (unsigned long long)(~row);
        atomicMax(&g_best[q], pk);
    }
}

__global__ void gather(const float* __restrict__ actions,
                       float* __restrict__ out, int Q) {
    int q = blockIdx.x;
    int t = threadIdx.x;
    unsigned int idx = ~(unsigned int)(g_best[q] & 0xFFFFFFFFull);
    out[(size_t)q * KD + t] = actions[(size_t)idx * KD + t];
    __syncthreads();
    if (t == 0) {
        g_best[q] = 0ull;
        g_seedkey[q] = 0u;
        if (q == 0) g_ccnt = 0;
    }
}

extern "C" void kernel_launch(void* const* d_in, const int* in_sizes, int n_in,
                              void* d_out, int out_size) {
    int ip = 0, ia = 1;
    if (n_in >= 2 && in_sizes[0] > in_sizes[1]) { ip = 1; ia = 0; }
    const float* pred    = (const float*)d_in[ip];
    const float* actions = (const float*)d_in[ia];
    int Q = in_sizes[ip] / KD;
    if (Q > QMAX) Q = QMAX;
    int N = in_sizes[ia] / KD;

    prepass<<<PGRID, 256>>>(actions, pred, N, Q);
    sim_argmax<<<GRIDX, TPB>>>(actions, pred, N, Q);
    rescore<<<148, 256>>>(actions, pred, N);
    gather<<<Q, KD>>>(actions, (float*)d_out, Q);
}

// round 16
// speedup vs baseline: 1.2803x; 1.0828x over previous
#include <cuda_runtime.h>
#include <cuda_fp16.h>
#include <cstdint>

// ContinousActionDecoder, filter-and-rescue, 3-CTA/SM fp16 screen:
//  Raw (unnormalized) fp16 A-frags packed straight from GMEM; screening
//  compares d >= t[q]*||a|| via FMA (norm folded into the threshold side).
//  Barrier-free hot loop, 6 warps/SMSP for latency hiding, dynamic
//  per-query thresholds seeded by exact prepass; exact fp32 rescore.

#define KD      64
#define QMAX    128
#define BM      128
#define TPB     256
#define GRIDX   444
#define MARGIN  2.5e-3f
#define CAP     (1 << 21)
#define SROWS   32
#define PGRID   148

__device__ unsigned long long g_best[QMAX];       // static zero-init
__device__ unsigned int g_seedkey[QMAX];
__device__ int g_ccnt;
__device__ unsigned long long g_cand[CAP];

__device__ __forceinline__ unsigned int fkey(float f) {
    unsigned int u = __float_as_uint(f);
    return (u & 0x80000000u) ? ~u : (u | 0x80000000u);
}
__device__ __forceinline__ float unfkey(unsigned int k) {
    unsigned int u = (k & 0x80000000u) ? (k ^ 0x80000000u) : ~k;
    return __uint_as_float(u);
}
__device__ __forceinline__ uint32_t h2pack(float lo, float hi) {
    uint32_t r;
    asm("cvt.rn.f16x2.f32 %0, %1, %2;" : "=r"(r) : "f"(hi), "f"(lo));
    return r;
}
#define MMA_F16(d, a0,a1,a2,a3, b0,b1) \
    asm volatile("mma.sync.aligned.m16n8k16.row.col.f32.f16.f16.f32 " \
        "{%0,%1,%2,%3}, {%4,%5,%6,%7}, {%8,%9}, {%0,%1,%2,%3};" \
        : "+f"((d)[0]), "+f"((d)[1]), "+f"((d)[2]), "+f"((d)[3]) \
        : "r"(a0), "r"(a1), "r"(a2), "r"(a3), "r"(b0), "r"(b1))

#define EMIT_IF(cond, q, row, s) do {                                   \
    if (cond) {                                                         \
        atomicMax(&g_seedkey[(q)], fkey(s));                            \
        int _idx = atomicAdd(&g_ccnt, 1);                               \
        if (_idx < CAP)                                                 \
            g_cand[_idx] = ((unsigned long long)(unsigned)(q) << 32) |  \
                           (unsigned long long)(unsigned)(row);         \
    }                                                                   \
} while (0)

// ---------------- prepass: exact sample scores -> per-query seed ----------
__global__ void __launch_bounds__(256)
prepass(const float* __restrict__ actions, const float* __restrict__ pred,
        int N, int Q)
{
    __shared__ float qn[QMAX * KD];
    __shared__ float rows[SROWS * KD];
    __shared__ float rinv[SROWS];
    __shared__ float qinv[QMAX];
    __shared__ unsigned int skey[QMAX];

    const int tid = threadIdx.x;
    if (tid < QMAX) {
        float iv = 0.f;
        if (tid < Q) {
            float ss = 0.f;
            for (int k = 0; k < KD; ++k) {
                float v = pred[tid * KD + k];
                ss = fmaf(v, v, ss);
            }
            iv = (ss > 1e-30f) ? rsqrtf(ss) : 0.f;
        }
        qinv[tid] = iv;
        skey[tid] = 0u;
    }
    __syncthreads();
    for (int i = tid; i < QMAX * KD; i += 256) {
        int q = i >> 6, k = i & 63;
        qn[i] = (q < Q) ? pred[q * KD + k] * qinv[q] : 0.f;
    }
    const long long total = (long long)PGRID * SROWS;
    for (int i = tid; i < SROWS * 16; i += 256) {
        int r = i >> 4, k4 = i & 15;
        long long si = (long long)blockIdx.x * SROWS + r;
        long long gr = si * N / total;
        if (gr >= N) gr = N - 1;
        *(float4*)&rows[r * KD + k4 * 4] =
            ((const float4*)actions)[gr * (KD / 4) + k4];
    }
    __syncthreads();
    if (tid < SROWS) {
        float ss = 0.f;
        for (int k = 0; k < KD; ++k) {
            float v = rows[tid * KD + k];
            ss = fmaf(v, v, ss);
        }
        rinv[tid] = (ss > 1e-30f) ? rsqrtf(ss) : 0.f;
    }
    __syncthreads();

    const int rl = tid >> 3;
    const int qg = tid & 7;
    float4 rv[16];
#pragma unroll
    for (int k = 0; k < 16; ++k) rv[k] = *(const float4*)&rows[rl * KD + k * 4];
    const float ri = rinv[rl];
#pragma unroll
    for (int j = 0; j < 16; ++j) {
        int q = qg + j * 8;
        const float4* qp = (const float4*)&qn[q * KD];
        float dot = 0.f;
#pragma unroll
        for (int k = 0; k < 16; ++k) {
            float4 b = qp[k];
            dot = fmaf(rv[k].x, b.x, dot);
            dot = fmaf(rv[k].y, b.y, dot);
            dot = fmaf(rv[k].z, b.z, dot);
            dot = fmaf(rv[k].w, b.w, dot);
        }
        if (q < Q) atomicMax(&skey[q], fkey(dot * ri));
    }
    __syncthreads();
    if (tid < QMAX && tid < Q) atomicMax(&g_seedkey[tid], skey[tid]);
}

// ---------------- phase 1: screened MMA, norm folded into threshold -------
extern "C" __global__ void __launch_bounds__(TPB, 3)
sim_argmax(const float* __restrict__ actions, const float* __restrict__ pred,
           int N, int Q)
{
    __shared__ float invb[QMAX];
    __shared__ float tf_s[QMAX];
    __shared__ uint2 Bf[2048];                 // 16 KB query frags

    const int tid  = threadIdx.x;
    const int lane = tid & 31;
    const int w    = tid >> 5;
    const int rw   = lane >> 2;
    const int c4   = lane & 3;
    const int Rb   = w * 16;

    if (tid < QMAX) {
        float iv = 0.f;
        if (tid < Q) {
            float ss = 0.f;
            for (int k = 0; k < KD; ++k) {
                float v = pred[tid * KD + k];
                ss = fmaf(v, v, ss);
            }
            iv = (ss > 1e-30f) ? rsqrtf(ss) : 0.f;
        }
        invb[tid] = iv;
        tf_s[tid] = (tid < Q) ? (unfkey(g_seedkey[tid]) - MARGIN) : 3.4e38f;
    }
    __syncthreads();

    // B fragments once: [ks][nt][lane] -> uint2 {bh(k0,k1), bh(k+8)}
#pragma unroll
    for (int i = 0; i < 8; ++i) {
        int slot = tid + i * TPB;              // 0..2047
        int ks = slot >> 9;
        int nt = (slot >> 5) & 15;
        int l  = slot & 31;
        int q  = nt * 8 + (l >> 2);
        int k0 = ks * 16 + (l & 3) * 2;
        float iv = invb[q];
        float x0 = 0.f, x1 = 0.f, x2 = 0.f, x3 = 0.f;
        if (q < Q) {
            x0 = pred[q * KD + k0]     * iv;
            x1 = pred[q * KD + k0 + 1] * iv;
            x2 = pred[q * KD + k0 + 8] * iv;
            x3 = pred[q * KD + k0 + 9] * iv;
        }
        uint2 v;
        v.x = h2pack(x0, x1);
        v.y = h2pack(x2, x3);
        Bf[slot] = v;
    }
    __syncthreads();                            // last barrier before loop

    const long long ntiles = ((long long)N + BM - 1) / BM;
    long long tile = blockIdx.x;

    int it = 0;
    for (; tile < ntiles; tile += GRIDX, ++it) {
        // ---- load rows, exact fp32 norms, pack RAW fp16 frags (L dies fast)
        long long r0c = tile * BM + Rb + rw;
        long long r1c = r0c + 8;
        if (r0c >= N) r0c = N - 1;
        if (r1c >= N) r1c = N - 1;
        const float2* p0 = (const float2*)(actions + r0c * KD) + c4;
        const float2* p1 = (const float2*)(actions + r1c * KD) + c4;

        uint32_t A[16];
        float sa0 = 0.f, sa1 = 0.f, sb0 = 0.f, sb1 = 0.f;
#pragma unroll
        for (int m = 0; m < 8; ++m) {
            float2 v0 = p0[4 * m];
            float2 v1 = p1[4 * m];
            // A[4*ks + {0,2}] rows r0 (m = 2ks, 2ks+1); {1,3} rows r1
            int ks = m >> 1, half = m & 1;
            A[4 * ks + 2 * half]     = h2pack(v0.x, v0.y);
            A[4 * ks + 2 * half + 1] = h2pack(v1.x, v1.y);
            if (half == 0) {
                sa0 = fmaf(v0.x, v0.x, sa0); sa0 = fmaf(v0.y, v0.y, sa0);
                sa1 = fmaf(v1.x, v1.x, sa1); sa1 = fmaf(v1.y, v1.y, sa1);
            } else {
                sb0 = fmaf(v0.x, v0.x, sb0); sb0 = fmaf(v0.y, v0.y, sb0);
                sb1 = fmaf(v1.x, v1.x, sb1); sb1 = fmaf(v1.y, v1.y, sb1);
            }
        }
        float ss0 = sa0 + sb0, ss1 = sa1 + sb1;
        ss0 += __shfl_xor_sync(0xffffffffu, ss0, 1);
        ss0 += __shfl_xor_sync(0xffffffffu, ss0, 2);
        ss1 += __shfl_xor_sync(0xffffffffu, ss1, 1);
        ss1 += __shfl_xor_sync(0xffffffffu, ss1, 2);
        float nrm0 = fmaxf(sqrtf(ss0), 1e-15f);
        float nrm1 = fmaxf(sqrtf(ss1), 1e-15f);

        // ---- periodic threshold refresh (racing, monotone-safe)
        if ((it & 7) == 7) {
            for (int j = lane; j < QMAX; j += 32)
                tf_s[j] = fmaxf(tf_s[j], unfkey(g_seedkey[j]) - MARGIN);
        }

        const long long r0g = tile * BM + Rb + rw;
        const bool ok0 = (r0g < N), ok1 = (r0g + 8 < N);

#pragma unroll
        for (int hf = 0; hf < 2; ++hf) {
            float d[8][4];
#pragma unroll
            for (int n = 0; n < 8; ++n)
#pragma unroll
                for (int c = 0; c < 4; ++c) d[n][c] = 0.f;

#pragma unroll
            for (int ks = 0; ks < 4; ++ks) {
#pragma unroll
                for (int n = 0; n < 8; ++n) {
                    uint2 b = Bf[(ks * 16 + hf * 8 + n) * 32 + lane];
                    MMA_F16(d[n], A[4 * ks], A[4 * ks + 1],
                            A[4 * ks + 2], A[4 * ks + 3], b.x, b.y);
                }
            }

            // branch-free screening: d - t[q]*nrm via FMA
            float mx = -3.4e38f;
#pragma unroll
            for (int n = 0; n < 8; ++n) {
                int j = hf * 8 + n;
                float t0f = tf_s[j * 8 + 2 * c4];
                float t1f = tf_s[j * 8 + 2 * c4 + 1];
                float m01 = fmaxf(fmaf(-t0f, nrm0, d[n][0]),
                                  fmaf(-t1f, nrm0, d[n][1]));
                float m23 = fmaxf(fmaf(-t0f, nrm1, d[n][2]),
                                  fmaf(-t1f, nrm1, d[n][3]));
                mx = fmaxf(mx, fmaxf(m01, m23));
            }
            if (__any_sync(0xffffffffu, mx >= 0.f)) {
                float i0 = __fdividef(1.f, nrm0);
                float i1 = __fdividef(1.f, nrm1);
#pragma unroll
                for (int n = 0; n < 8; ++n) {
                    int j = hf * 8 + n;
                    int q0 = j * 8 + 2 * c4;
                    float t0f = tf_s[q0], t1f = tf_s[q0 + 1];
                    EMIT_IF(ok0 && d[n][0] >= t0f * nrm0, q0,     r0g,
                            d[n][0] * i0);
                    EMIT_IF(ok0 && d[n][1] >= t1f * nrm0, q0 + 1, r0g,
                            d[n][1] * i0);
                    EMIT_IF(ok1 && d[n][2] >= t0f * nrm1, q0,     r0g + 8,
                            d[n][2] * i1);
                    EMIT_IF(ok1 && d[n][3] >= t1f * nrm1, q0 + 1, r0g + 8,
                            d[n][3] * i1);
                }
            }
        }
    }
}

// ---------------- phase 2: exact rescore ----------------------------------
extern "C" __global__ void rescore(const float* __restrict__ actions,
                                   const float* __restrict__ pred, int N)
{
    int total = g_ccnt;
    if (total > CAP) total = CAP;
    const int stride = gridDim.x * blockDim.x;
    for (int i = blockIdx.x * blockDim.x + threadIdx.x; i < total; i += stride) {
        unsigned long long c = g_cand[i];
        int q = (int)(c >> 32);
        unsigned row = (unsigned)c;
        const float4* a = (const float4*)(actions + (size_t)row * KD);
        const float4* b = (const float4*)(pred + (size_t)q * KD);
        float dot = 0.f, na = 0.f;
#pragma unroll
        for (int j = 0; j < 16; ++j) {
            float4 av = a[j], bv = b[j];
            dot = fmaf(av.x, bv.x, dot);
            dot = fmaf(av.y, bv.y, dot);
            dot = fmaf(av.z, bv.z, dot);
            dot = fmaf(av.w, bv.w, dot);
            na = fmaf(av.x, av.x, na);
            na = fmaf(av.y, av.y, na);
            na = fmaf(av.z, av.z, na);
            na = fmaf(av.w, av.w, na);
        }
        float s = dot / sqrtf(fmaxf(na, 1e-30f));
        unsigned long long pk = ((unsigned long long)fkey(s) << 32) |
                                (unsigned long long)(~row);
        atomicMax(&g_best[q], pk);
    }
}

__global__ void gather(const float* __restrict__ actions,
                       float* __restrict__ out, int Q) {
    int q = blockIdx.x;
    int t = threadIdx.x;
    unsigned int idx = ~(unsigned int)(g_best[q] & 0xFFFFFFFFull);
    out[(size_t)q * KD + t] = actions[(size_t)idx * KD + t];
    __syncthreads();
    if (t == 0) {
        g_best[q] = 0ull;
        g_seedkey[q] = 0u;
        if (q == 0) g_ccnt = 0;
    }
}

extern "C" void kernel_launch(void* const* d_in, const int* in_sizes, int n_in,
                              void* d_out, int out_size) {
    int ip = 0, ia = 1;
    if (n_in >= 2 && in_sizes[0] > in_sizes[1]) { ip = 1; ia = 0; }
    const float* pred    = (const float*)d_in[ip];
    const float* actions = (const float*)d_in[ia];
    int Q = in_sizes[ip] / KD;
    if (Q > QMAX) Q = QMAX;
    int N = in_sizes[ia] / KD;

    prepass<<<PGRID, 256>>>(actions, pred, N, Q);
    sim_argmax<<<GRIDX, TPB>>>(actions, pred, N, Q);
    rescore<<<148, 256>>>(actions, pred, N);
    gather<<<Q, KD>>>(actions, (float*)d_out, Q);
}